// round 10
// baseline (speedup 1.0000x reference)
#include <cuda_runtime.h>
#include <cuda_fp16.h>
#include <cstdint>

#define Bq 64
#define Tq 512
#define Iq 1024
#define Hq 1024
#define G4 4096
#define BT 32768
#define NCTA 128
#define HSTR 1032
#define GSTR 33
#define RSMEM 217216

__device__ __half g_x16[(size_t)BT * Iq];
__device__ __half g_h1[(size_t)BT * Hq];
__device__ __half g_h2[(size_t)BT * Hq];
__device__ __half g_wih[(size_t)3 * G4 * Iq];
__device__ __half g_whh[(size_t)3 * G4 * Hq];
__device__ float  g_bias[3 * G4];
__device__ float  g_xproj[(size_t)BT * G4];
__device__ __half g_hring[(size_t)4 * Bq * Hq];
__device__ unsigned g_flag[(Tq + 1) * 8];
__device__ unsigned g_bar_count;
__device__ unsigned g_bar_gen;

__device__ __forceinline__ void cp_async16(void* smem, const void* g) {
    uint32_t s = (uint32_t)__cvta_generic_to_shared(smem);
    asm volatile("cp.async.cg.shared.global [%0], [%1], 16;\n" :: "r"(s), "l"(g));
}
#define CP_COMMIT asm volatile("cp.async.commit_group;\n" ::: "memory")
#define CP_WAIT(n) asm volatile("cp.async.wait_group %0;\n" :: "n"(n) : "memory")

__device__ __forceinline__ void mbar_init(uint32_t addr, unsigned count) {
    asm volatile("mbarrier.init.shared.b64 [%0], %1;\n" :: "r"(addr), "r"(count) : "memory");
}
__device__ __forceinline__ void cp_async_mbar_arrive(uint32_t addr) {
    asm volatile("cp.async.mbarrier.arrive.noinc.shared.b64 [%0];\n" :: "r"(addr) : "memory");
}
__device__ __forceinline__ void mbar_wait_parity(uint32_t addr, unsigned parity) {
    asm volatile(
        "{\n\t"
        ".reg .pred P1;\n\t"
        "LAB_WAIT_%=:\n\t"
        "mbarrier.try_wait.parity.shared.b64 P1, [%0], %1;\n\t"
        "@P1 bra.uni LAB_DONE_%=;\n\t"
        "bra.uni LAB_WAIT_%=;\n\t"
        "LAB_DONE_%=:\n\t"
        "}"
        :: "r"(addr), "r"(parity) : "memory");
}

__device__ __forceinline__ void ldsm_x4(uint32_t& r0, uint32_t& r1, uint32_t& r2, uint32_t& r3,
                                        const __half* p) {
    uint32_t s = (uint32_t)__cvta_generic_to_shared(p);
    asm volatile("ldmatrix.sync.aligned.m8n8.x4.shared.b16 {%0,%1,%2,%3}, [%4];\n"
                 : "=r"(r0), "=r"(r1), "=r"(r2), "=r"(r3) : "r"(s));
}

__device__ __forceinline__ void mma16816(float* c, uint32_t a0, uint32_t a1, uint32_t a2, uint32_t a3,
                                         uint32_t b0, uint32_t b1) {
    asm volatile(
        "mma.sync.aligned.m16n8k16.row.col.f32.f16.f16.f32 "
        "{%0,%1,%2,%3}, {%4,%5,%6,%7}, {%8,%9}, {%0,%1,%2,%3};\n"
        : "+f"(c[0]), "+f"(c[1]), "+f"(c[2]), "+f"(c[3])
        : "r"(a0), "r"(a1), "r"(a2), "r"(a3), "r"(b0), "r"(b1));
}

__device__ __forceinline__ float tanh_fast(float x) {
    float r;
    asm("tanh.approx.f32 %0, %1;\n" : "=f"(r) : "f"(x));
    return r;
}
__device__ __forceinline__ float sigmoid_fast(float x) {
    return __fdividef(1.f, 1.f + __expf(-x));
}

__device__ __forceinline__ void grid_barrier() {
    __syncthreads();
    if (threadIdx.x == 0) {
        __threadfence();
        volatile unsigned* vgen = &g_bar_gen;
        unsigned gen = *vgen;
        if (atomicAdd(&g_bar_count, 1u) == NCTA - 1) {
            atomicExch(&g_bar_count, 0u);
            __threadfence();
            atomicExch((unsigned*)&g_bar_gen, gen + 1u);
        } else {
            while (*vgen == gen) {}
        }
        __threadfence();
    }
    __syncthreads();
}

__global__ void dummy_kernel() {}

__global__ void prep_kernel(const float* __restrict__ x, const float* __restrict__ wih,
                            const float* __restrict__ whh, const float* __restrict__ bih,
                            const float* __restrict__ bhh) {
    size_t i0 = (size_t)blockIdx.x * blockDim.x + threadIdx.x;
    size_t stride = (size_t)gridDim.x * blockDim.x;
    for (size_t i = i0; i < (size_t)BT * Iq; i += stride) g_x16[i] = __float2half(x[i]);
    for (size_t i = i0; i < (size_t)3 * G4 * Iq; i += stride) {
        g_wih[i] = __float2half(wih[i]);
        g_whh[i] = __float2half(whh[i]);
    }
    for (size_t i = i0; i < (size_t)3 * G4; i += stride) g_bias[i] = bih[i] + bhh[i];
}

// xproj[BT,4096] = A[BT,1024] * W[4096,1024]^T + bias
#define PSTR 40
__global__ void __launch_bounds__(256, 2) proj_kernel(const __half* __restrict__ A,
                                                      const __half* __restrict__ W,
                                                      const float* __restrict__ bias,
                                                      float* __restrict__ C) {
    __shared__ __half sA[2][128 * PSTR];
    __shared__ __half sB[2][128 * PSTR];
    const int tid = threadIdx.x, lane = tid & 31, w = tid >> 5;
    const int m0 = blockIdx.x * 128, n0 = blockIdx.y * 128;
    const int wm = (w & 3) * 32, wn = (w >> 2) * 64;

    float acc[2][8][4];
#pragma unroll
    for (int i = 0; i < 2; i++)
#pragma unroll
        for (int j = 0; j < 8; j++)
#pragma unroll
            for (int k = 0; k < 4; k++) acc[i][j][k] = 0.f;

    auto load = [&](int buf, int k0) {
#pragma unroll
        for (int c = 0; c < 4; c++) {
            int id = tid + c * 256;
            int isB = id >> 9;
            int cc = id & 511;
            int r = cc >> 2, q = cc & 3;
            const __half* src = (isB ? W + (size_t)(n0 + r) * Iq : A + (size_t)(m0 + r) * Iq) + k0 + q * 8;
            __half* dst = (isB ? sB[buf] : sA[buf]) + r * PSTR + q * 8;
            cp_async16(dst, src);
        }
    };

    auto compute = [&](int buf) {
#pragma unroll
        for (int kk = 0; kk < 32; kk += 16) {
            uint32_t a[2][4];
#pragma unroll
            for (int mt = 0; mt < 2; mt++) {
                int row = wm + mt * 16 + (lane & 7) + ((lane >> 3) & 1) * 8;
                int col = kk + (lane >> 4) * 8;
                ldsm_x4(a[mt][0], a[mt][1], a[mt][2], a[mt][3], &sA[buf][row * PSTR + col]);
            }
            uint32_t bf[8][2];
#pragma unroll
            for (int nt2 = 0; nt2 < 4; nt2++) {
                int row = wn + nt2 * 16 + (lane & 7) + ((lane >> 3) & 1) * 8;
                int col = kk + (lane >> 4) * 8;
                uint32_t r0, r1, r2, r3;
                ldsm_x4(r0, r1, r2, r3, &sB[buf][row * PSTR + col]);
                bf[nt2 * 2][0] = r0; bf[nt2 * 2 + 1][0] = r1;
                bf[nt2 * 2][1] = r2; bf[nt2 * 2 + 1][1] = r3;
            }
#pragma unroll
            for (int mt = 0; mt < 2; mt++)
#pragma unroll
                for (int nt = 0; nt < 8; nt++)
                    mma16816(acc[mt][nt], a[mt][0], a[mt][1], a[mt][2], a[mt][3], bf[nt][0], bf[nt][1]);
        }
    };

    load(0, 0);
    CP_COMMIT;
    int buf = 0;
    for (int it = 0; it < 32; it++) {
        CP_WAIT(0);
        __syncthreads();
        if (it + 1 < 32) { load(buf ^ 1, (it + 1) * 32); CP_COMMIT; }
        compute(buf);
        buf ^= 1;
    }

    const int gid = lane >> 2, t4 = lane & 3;
#pragma unroll
    for (int nt = 0; nt < 8; nt++) {
        int col = n0 + wn + nt * 8 + t4 * 2;
        float b0 = bias[col], b1 = bias[col + 1];
#pragma unroll
        for (int mt = 0; mt < 2; mt++) {
            int r0 = m0 + wm + mt * 16 + gid;
            float2 v0 = make_float2(acc[mt][nt][0] + b0, acc[mt][nt][1] + b1);
            float2 v1 = make_float2(acc[mt][nt][2] + b0, acc[mt][nt][3] + b1);
            *(float2*)&C[(size_t)r0 * G4 + col] = v0;
            *(float2*)&C[(size_t)(r0 + 8) * G4 + col] = v1;
        }
    }
}

// persistent recurrence: 128 CTAs x 512 threads (16 warps).
// warp w = (kh = w>>3, tile = w&7): computes 16x16 gate tile over K-half kh into gs[kh].
// warp w also stages 64-col chunk w (8KB) after waiting producer flag group w>>1.
// Consumers wait per-chunk mbarriers in rotated order; epilogue sums the two K-halves.
__global__ void __launch_bounds__(512, 1) rec_kernel(const float* __restrict__ xproj,
                                                     const __half* __restrict__ Whh,
                                                     __half* __restrict__ hbuf_out,
                                                     float* __restrict__ out32) {
    extern __shared__ __align__(16) unsigned char smem_raw[];
    __half* ws = (__half*)smem_raw;                 // [32][HSTR] Whh slice
    __half* hs = ws + 32 * HSTR;                    // [64][HSTR] h_prev
    float* gs = (float*)(smem_raw + 198144);        // [2][64][GSTR] partial gates
    float* cs = (float*)(smem_raw + 215040);        // [512] cell state
    const uint32_t mbar0 = (uint32_t)__cvta_generic_to_shared(smem_raw + 217088); // 16 mbarriers

    const int tid = threadIdx.x, lane = tid & 31, w = tid >> 5;
    const int bid = blockIdx.x;
    const int j0 = bid * 8;
    const int kh = w >> 3, tile = w & 7;
    const int wm = (tile & 3) * 16, wn = (tile >> 2) * 16;
    float* gsh = gs + kh * 64 * GSTR;

    for (int c = tid; c < 32 * 128; c += 512) {
        int n = c >> 7, q = c & 127;
        int grow = (n >> 3) * Hq + j0 + (n & 7);
        cp_async16(ws + n * HSTR + q * 8, Whh + (size_t)grow * Hq + q * 8);
    }
    CP_COMMIT;
    cs[tid] = 0.f;
    if (tid < 256) ((uint32_t*)g_hring)[bid * 256 + tid] = 0u;
    {
        int gid = bid * 512 + tid;
        if (gid < (Tq + 1) * 8) g_flag[gid] = 0u;
        if (bid == 0 && tid < 8) g_flag[tid] = 16u;
        if (tid < 16) mbar_init(mbar0 + tid * 8, 32u);
    }
    CP_WAIT(0);
    grid_barrier();

    for (int t = 0; t < Tq; t++) {
        const unsigned parity = t & 1u;
        // prefetch this step's xproj gate biases (1 hidden unit per thread)
        const int b = tid >> 3, jj = tid & 7;
        float xv[4];
        {
            size_t base = ((size_t)b * Tq + t) * G4 + j0 + jj;
            xv[0] = xproj[base];
            xv[1] = xproj[base + Hq];
            xv[2] = xproj[base + 2 * Hq];
            xv[3] = xproj[base + 3 * Hq];
        }

        const __half* hsrc = g_hring + (size_t)(t & 3) * (Bq * Hq);

        // warp w: wait for producer group w>>1 of h_t, stage 64-col chunk w, arrive mbar[w]
        if (lane == 0) {
            unsigned v;
            const unsigned* f = &g_flag[t * 8 + (w >> 1)];
            do {
                asm volatile("ld.acquire.gpu.u32 %0, [%1];" : "=r"(v) : "l"(f) : "memory");
            } while (v < 16u);
        }
        __syncwarp();
#pragma unroll
        for (int i2 = 0; i2 < 16; i2++) {
            int c = lane + i2 * 32;
            int r = c >> 3, q = c & 7;           // 64 rows x 8 16B-units (64 cols)
            cp_async16(hs + r * HSTR + w * 64 + q * 8, hsrc + r * Hq + w * 64 + q * 8);
        }
        cp_async_mbar_arrive(mbar0 + w * 8);

        // MMA over this warp's K-half (8 chunks of 64 cols), rotated chunk order
        float acc0[4] = {0.f, 0.f, 0.f, 0.f}, acc1[4] = {0.f, 0.f, 0.f, 0.f};
#pragma unroll
        for (int i = 0; i < 8; i++) {
            const int c = kh * 8 + (((w & 7) + i) & 7);
            mbar_wait_parity(mbar0 + c * 8, parity);
#pragma unroll
            for (int kk = 0; kk < 64; kk += 16) {
                int k = c * 64 + kk;
                uint32_t a0, a1, a2, a3, b0, b1, b2, b3;
                {
                    int row = wm + (lane & 7) + ((lane >> 3) & 1) * 8;
                    int col = k + (lane >> 4) * 8;
                    ldsm_x4(a0, a1, a2, a3, hs + row * HSTR + col);
                }
                {
                    int row = wn + (lane & 7) + ((lane >> 3) & 1) * 8;
                    int col = k + (lane >> 4) * 8;
                    ldsm_x4(b0, b1, b2, b3, ws + row * HSTR + col);
                }
                mma16816(acc0, a0, a1, a2, a3, b0, b2);
                mma16816(acc1, a0, a1, a2, a3, b1, b3);
            }
        }
        {
            const int gid = lane >> 2, t4 = lane & 3;
            int r0 = wm + gid;
            int c0 = wn + t4 * 2;
            gsh[r0 * GSTR + c0] = acc0[0];           gsh[r0 * GSTR + c0 + 1] = acc0[1];
            gsh[(r0 + 8) * GSTR + c0] = acc0[2];     gsh[(r0 + 8) * GSTR + c0 + 1] = acc0[3];
            gsh[r0 * GSTR + c0 + 8] = acc1[0];       gsh[r0 * GSTR + c0 + 9] = acc1[1];
            gsh[(r0 + 8) * GSTR + c0 + 8] = acc1[2]; gsh[(r0 + 8) * GSTR + c0 + 9] = acc1[3];
        }
        __syncthreads();

        // elementwise: one hidden unit per thread; sum the two K-half partials
        float hval;
        {
            const float* g0 = gs + b * GSTR;
            const float* g1 = gs + (64 + b) * GSTR;
            float ig = g0[jj]      + g1[jj]      + xv[0];
            float fg = g0[8 + jj]  + g1[8 + jj]  + xv[1];
            float gg = g0[16 + jj] + g1[16 + jj] + xv[2];
            float og = g0[24 + jj] + g1[24 + jj] + xv[3];
            ig = sigmoid_fast(ig);
            fg = sigmoid_fast(fg);
            gg = tanh_fast(gg);
            og = sigmoid_fast(og);
            float c = fg * cs[tid] + ig * gg;
            cs[tid] = c;
            hval = og * tanh_fast(c);
            g_hring[(size_t)((t + 1) & 3) * (Bq * Hq) + b * Hq + j0 + jj] = __float2half(hval);
        }
        __syncthreads();
        // publish h_{t+1} availability BEFORE the (off-critical-path) output store
        if (tid == 0) {
            __threadfence();
            atomicAdd(&g_flag[(t + 1) * 8 + (bid >> 4)], 1u);
        }
        {
            size_t oidx = ((size_t)b * Tq + t) * Hq + j0 + jj;
            if (out32) out32[oidx] = hval;
            else hbuf_out[oidx] = __float2half(hval);
        }
    }
}

extern "C" void kernel_launch(void* const* d_in, const int* in_sizes, int n_in,
                              void* d_out, int out_size) {
    const float* x   = (const float*)d_in[0];
    const float* Wih = (const float*)d_in[1];
    const float* Whh = (const float*)d_in[2];
    const float* bih = (const float*)d_in[3];
    const float* bhh = (const float*)d_in[4];
    float* out = (float*)d_out;

    cudaFuncSetAttribute(rec_kernel, cudaFuncAttributeMaxDynamicSharedMemorySize, RSMEM);

    prep_kernel<<<2048, 256>>>(x, Wih, Whh, bih, bhh);
    dummy_kernel<<<1, 1>>>();   // keeps ncu -s 5 window on rec_kernel (layer 1)

    __half* g_x16_p;  cudaGetSymbolAddress((void**)&g_x16_p,  g_x16);
    __half* g_h1_p;   cudaGetSymbolAddress((void**)&g_h1_p,   g_h1);
    __half* g_h2_p;   cudaGetSymbolAddress((void**)&g_h2_p,   g_h2);
    __half* g_wih_p;  cudaGetSymbolAddress((void**)&g_wih_p,  g_wih);
    __half* g_whh_p;  cudaGetSymbolAddress((void**)&g_whh_p,  g_whh);
    float*  g_bias_p; cudaGetSymbolAddress((void**)&g_bias_p, g_bias);
    float*  g_xp_p;   cudaGetSymbolAddress((void**)&g_xp_p,   g_xproj);

    dim3 pgrid(BT / 128, G4 / 128);

    proj_kernel<<<pgrid, 256>>>(g_x16_p, g_wih_p, g_bias_p, g_xp_p);
    rec_kernel<<<NCTA, 512, RSMEM>>>(g_xp_p, g_whh_p, g_h1_p, nullptr);

    proj_kernel<<<pgrid, 256>>>(g_h1_p, g_wih_p + (size_t)G4 * Iq, g_bias_p + G4, g_xp_p);
    rec_kernel<<<NCTA, 512, RSMEM>>>(g_xp_p, g_whh_p + (size_t)G4 * Hq, g_h2_p, nullptr);

    proj_kernel<<<pgrid, 256>>>(g_h2_p, g_wih_p + (size_t)2 * G4 * Iq, g_bias_p + 2 * G4, g_xp_p);
    rec_kernel<<<NCTA, 512, RSMEM>>>(g_xp_p, g_whh_p + (size_t)2 * G4 * Hq, nullptr, out);
}

// round 11
// speedup vs baseline: 1.1194x; 1.1194x over previous
#include <cuda_runtime.h>
#include <cuda_fp16.h>
#include <cstdint>

#define Bq 64
#define Tq 512
#define Iq 1024
#define Hq 1024
#define G4 4096
#define BT 32768
#define NCTA 128
#define HSTR 1032
#define GSTR 33
#define RSMEM 217216

__device__ __half g_x16[(size_t)BT * Iq];
__device__ __half g_h1[(size_t)BT * Hq];
__device__ __half g_h2[(size_t)BT * Hq];
__device__ __half g_wih[(size_t)3 * G4 * Iq];
__device__ __half g_whh[(size_t)3 * G4 * Hq];
__device__ float  g_bias[3 * G4];
__device__ float  g_xproj[(size_t)BT * G4];
__device__ __half g_hring[(size_t)4 * Bq * Hq];
__device__ unsigned g_flag[(Tq + 1) * 8];
__device__ unsigned g_bar_count;
__device__ unsigned g_bar_gen;

__device__ __forceinline__ void cp_async16(void* smem, const void* g) {
    uint32_t s = (uint32_t)__cvta_generic_to_shared(smem);
    asm volatile("cp.async.cg.shared.global [%0], [%1], 16;\n" :: "r"(s), "l"(g));
}
#define CP_COMMIT asm volatile("cp.async.commit_group;\n" ::: "memory")
#define CP_WAIT(n) asm volatile("cp.async.wait_group %0;\n" :: "n"(n) : "memory")

__device__ __forceinline__ void mbar_init(uint32_t addr, unsigned count) {
    asm volatile("mbarrier.init.shared.b64 [%0], %1;\n" :: "r"(addr), "r"(count) : "memory");
}
__device__ __forceinline__ void cp_async_mbar_arrive(uint32_t addr) {
    asm volatile("cp.async.mbarrier.arrive.noinc.shared.b64 [%0];\n" :: "r"(addr) : "memory");
}
__device__ __forceinline__ void mbar_wait_parity(uint32_t addr, unsigned parity) {
    asm volatile(
        "{\n\t"
        ".reg .pred P1;\n\t"
        "LAB_WAIT_%=:\n\t"
        "mbarrier.try_wait.parity.shared.b64 P1, [%0], %1;\n\t"
        "@P1 bra.uni LAB_DONE_%=;\n\t"
        "bra.uni LAB_WAIT_%=;\n\t"
        "LAB_DONE_%=:\n\t"
        "}"
        :: "r"(addr), "r"(parity) : "memory");
}

__device__ __forceinline__ void ldsm_x4(uint32_t& r0, uint32_t& r1, uint32_t& r2, uint32_t& r3,
                                        const __half* p) {
    uint32_t s = (uint32_t)__cvta_generic_to_shared(p);
    asm volatile("ldmatrix.sync.aligned.m8n8.x4.shared.b16 {%0,%1,%2,%3}, [%4];\n"
                 : "=r"(r0), "=r"(r1), "=r"(r2), "=r"(r3) : "r"(s));
}

__device__ __forceinline__ void mma16816(float* c, uint32_t a0, uint32_t a1, uint32_t a2, uint32_t a3,
                                         uint32_t b0, uint32_t b1) {
    asm volatile(
        "mma.sync.aligned.m16n8k16.row.col.f32.f16.f16.f32 "
        "{%0,%1,%2,%3}, {%4,%5,%6,%7}, {%8,%9}, {%0,%1,%2,%3};\n"
        : "+f"(c[0]), "+f"(c[1]), "+f"(c[2]), "+f"(c[3])
        : "r"(a0), "r"(a1), "r"(a2), "r"(a3), "r"(b0), "r"(b1));
}

__device__ __forceinline__ float tanh_fast(float x) {
    float r;
    asm("tanh.approx.f32 %0, %1;\n" : "=f"(r) : "f"(x));
    return r;
}
__device__ __forceinline__ float sigmoid_fast(float x) {
    return __fdividef(1.f, 1.f + __expf(-x));
}

__device__ __forceinline__ void grid_barrier() {
    __syncthreads();
    if (threadIdx.x == 0) {
        __threadfence();
        volatile unsigned* vgen = &g_bar_gen;
        unsigned gen = *vgen;
        if (atomicAdd(&g_bar_count, 1u) == NCTA - 1) {
            atomicExch(&g_bar_count, 0u);
            __threadfence();
            atomicExch((unsigned*)&g_bar_gen, gen + 1u);
        } else {
            while (*vgen == gen) {}
        }
        __threadfence();
    }
    __syncthreads();
}

__global__ void dummy_kernel() {}

__global__ void prep_kernel(const float* __restrict__ x, const float* __restrict__ wih,
                            const float* __restrict__ whh, const float* __restrict__ bih,
                            const float* __restrict__ bhh) {
    size_t i0 = (size_t)blockIdx.x * blockDim.x + threadIdx.x;
    size_t stride = (size_t)gridDim.x * blockDim.x;
    for (size_t i = i0; i < (size_t)BT * Iq; i += stride) g_x16[i] = __float2half(x[i]);
    for (size_t i = i0; i < (size_t)3 * G4 * Iq; i += stride) {
        g_wih[i] = __float2half(wih[i]);
        g_whh[i] = __float2half(whh[i]);
    }
    for (size_t i = i0; i < (size_t)3 * G4; i += stride) g_bias[i] = bih[i] + bhh[i];
}

// xproj[BT,4096] = A[BT,1024] * W[4096,1024]^T + bias
#define PSTR 40
__global__ void __launch_bounds__(256, 2) proj_kernel(const __half* __restrict__ A,
                                                      const __half* __restrict__ W,
                                                      const float* __restrict__ bias,
                                                      float* __restrict__ C) {
    __shared__ __half sA[2][128 * PSTR];
    __shared__ __half sB[2][128 * PSTR];
    const int tid = threadIdx.x, lane = tid & 31, w = tid >> 5;
    const int m0 = blockIdx.x * 128, n0 = blockIdx.y * 128;
    const int wm = (w & 3) * 32, wn = (w >> 2) * 64;

    float acc[2][8][4];
#pragma unroll
    for (int i = 0; i < 2; i++)
#pragma unroll
        for (int j = 0; j < 8; j++)
#pragma unroll
            for (int k = 0; k < 4; k++) acc[i][j][k] = 0.f;

    auto load = [&](int buf, int k0) {
#pragma unroll
        for (int c = 0; c < 4; c++) {
            int id = tid + c * 256;
            int isB = id >> 9;
            int cc = id & 511;
            int r = cc >> 2, q = cc & 3;
            const __half* src = (isB ? W + (size_t)(n0 + r) * Iq : A + (size_t)(m0 + r) * Iq) + k0 + q * 8;
            __half* dst = (isB ? sB[buf] : sA[buf]) + r * PSTR + q * 8;
            cp_async16(dst, src);
        }
    };

    auto compute = [&](int buf) {
#pragma unroll
        for (int kk = 0; kk < 32; kk += 16) {
            uint32_t a[2][4];
#pragma unroll
            for (int mt = 0; mt < 2; mt++) {
                int row = wm + mt * 16 + (lane & 7) + ((lane >> 3) & 1) * 8;
                int col = kk + (lane >> 4) * 8;
                ldsm_x4(a[mt][0], a[mt][1], a[mt][2], a[mt][3], &sA[buf][row * PSTR + col]);
            }
            uint32_t bf[8][2];
#pragma unroll
            for (int nt2 = 0; nt2 < 4; nt2++) {
                int row = wn + nt2 * 16 + (lane & 7) + ((lane >> 3) & 1) * 8;
                int col = kk + (lane >> 4) * 8;
                uint32_t r0, r1, r2, r3;
                ldsm_x4(r0, r1, r2, r3, &sB[buf][row * PSTR + col]);
                bf[nt2 * 2][0] = r0; bf[nt2 * 2 + 1][0] = r1;
                bf[nt2 * 2][1] = r2; bf[nt2 * 2 + 1][1] = r3;
            }
#pragma unroll
            for (int mt = 0; mt < 2; mt++)
#pragma unroll
                for (int nt = 0; nt < 8; nt++)
                    mma16816(acc[mt][nt], a[mt][0], a[mt][1], a[mt][2], a[mt][3], bf[nt][0], bf[nt][1]);
        }
    };

    load(0, 0);
    CP_COMMIT;
    int buf = 0;
    for (int it = 0; it < 32; it++) {
        CP_WAIT(0);
        __syncthreads();
        if (it + 1 < 32) { load(buf ^ 1, (it + 1) * 32); CP_COMMIT; }
        compute(buf);
        buf ^= 1;
    }

    const int gid = lane >> 2, t4 = lane & 3;
#pragma unroll
    for (int nt = 0; nt < 8; nt++) {
        int col = n0 + wn + nt * 8 + t4 * 2;
        float b0 = bias[col], b1 = bias[col + 1];
#pragma unroll
        for (int mt = 0; mt < 2; mt++) {
            int r0 = m0 + wm + mt * 16 + gid;
            float2 v0 = make_float2(acc[mt][nt][0] + b0, acc[mt][nt][1] + b1);
            float2 v1 = make_float2(acc[mt][nt][2] + b0, acc[mt][nt][3] + b1);
            *(float2*)&C[(size_t)r0 * G4 + col] = v0;
            *(float2*)&C[(size_t)(r0 + 8) * G4 + col] = v1;
        }
    }
}

// persistent recurrence: 128 CTAs x 256 threads (8 warps), R8 staging skeleton.
// warp w = (kh = w>>2, mt = w&3): computes a 16x32 tile (rows wm..wm+15, all 32 gate
// cols) over K-half kh with 4 independent accumulators; partial sums in gs[kh].
// warp w stages 128-col chunk w after waiting flag group w; per-chunk mbarriers;
// warp's first consumed chunk is the one it staged.
__global__ void __launch_bounds__(256, 1) rec_kernel(const float* __restrict__ xproj,
                                                     const __half* __restrict__ Whh,
                                                     __half* __restrict__ hbuf_out,
                                                     float* __restrict__ out32) {
    extern __shared__ __align__(16) unsigned char smem_raw[];
    __half* ws = (__half*)smem_raw;                 // [32][HSTR] Whh slice
    __half* hs = ws + 32 * HSTR;                    // [64][HSTR] h_prev
    float* gs = (float*)(smem_raw + 198144);        // [2][64][GSTR] partial gates
    float* cs = (float*)(smem_raw + 215040);        // [512] cell state
    const uint32_t mbar0 = (uint32_t)__cvta_generic_to_shared(smem_raw + 217088); // 8 mbarriers

    const int tid = threadIdx.x, lane = tid & 31, w = tid >> 5;
    const int bid = blockIdx.x;
    const int j0 = bid * 8;
    const int kh = w >> 2, mt = w & 3;
    const int wm = mt * 16;
    float* gsh = gs + kh * 64 * GSTR;

    for (int c = tid; c < 32 * 128; c += 256) {
        int n = c >> 7, q = c & 127;
        int grow = (n >> 3) * Hq + j0 + (n & 7);
        cp_async16(ws + n * HSTR + q * 8, Whh + (size_t)grow * Hq + q * 8);
    }
    CP_COMMIT;
    cs[tid] = 0.f; cs[tid + 256] = 0.f;
    ((uint32_t*)g_hring)[bid * 256 + tid] = 0u;
    {
        int gid = bid * 256 + tid;
        if (gid < (Tq + 1) * 8) g_flag[gid] = 0u;
        if (bid == 0 && tid < 8) g_flag[tid] = 16u;
        if (tid < 8) mbar_init(mbar0 + tid * 8, 32u);
    }
    CP_WAIT(0);
    grid_barrier();

    for (int t = 0; t < Tq; t++) {
        const unsigned parity = t & 1u;
        // prefetch this step's xproj gate biases (2 hidden units per thread)
        float xv[8];
#pragma unroll
        for (int qq = 0; qq < 2; qq++) {
            int p = tid + qq * 256;
            int b = p >> 3, jj = p & 7;
            size_t base = ((size_t)b * Tq + t) * G4 + j0 + jj;
            xv[qq * 4 + 0] = xproj[base];
            xv[qq * 4 + 1] = xproj[base + Hq];
            xv[qq * 4 + 2] = xproj[base + 2 * Hq];
            xv[qq * 4 + 3] = xproj[base + 3 * Hq];
        }

        const __half* hsrc = g_hring + (size_t)(t & 3) * (Bq * Hq);

        // warp w: wait for producer group w of h_t, stage k-chunk w, arrive on mbar[w]
        if (lane == 0) {
            unsigned v;
            const unsigned* f = &g_flag[t * 8 + w];
            do {
                asm volatile("ld.acquire.gpu.u32 %0, [%1];" : "=r"(v) : "l"(f) : "memory");
            } while (v < 16u);
        }
        __syncwarp();
#pragma unroll
        for (int i2 = 0; i2 < 32; i2++) {
            int c = lane + i2 * 32;
            int r = c >> 4, q = c & 15;
            cp_async16(hs + r * HSTR + w * 128 + q * 8, hsrc + r * Hq + w * 128 + q * 8);
        }
        cp_async_mbar_arrive(mbar0 + w * 8);

        // MMA: 16x32 tile over this warp's K-half, 4 chunks in rotated order
        float acc[4][4];
#pragma unroll
        for (int n = 0; n < 4; n++)
#pragma unroll
            for (int q = 0; q < 4; q++) acc[n][q] = 0.f;
#pragma unroll
        for (int i = 0; i < 4; i++) {
            const int c = kh * 4 + ((mt + i) & 3);
            mbar_wait_parity(mbar0 + c * 8, parity);
#pragma unroll
            for (int kk = 0; kk < 128; kk += 16) {
                int k = c * 128 + kk;
                uint32_t a0, a1, a2, a3;
                {
                    int row = wm + (lane & 7) + ((lane >> 3) & 1) * 8;
                    int col = k + (lane >> 4) * 8;
                    ldsm_x4(a0, a1, a2, a3, hs + row * HSTR + col);
                }
                uint32_t b0, b1, b2, b3, b4, b5, b6, b7;
                {
                    int row = (lane & 7) + ((lane >> 3) & 1) * 8;
                    int col = k + (lane >> 4) * 8;
                    ldsm_x4(b0, b1, b2, b3, ws + row * HSTR + col);
                    ldsm_x4(b4, b5, b6, b7, ws + (row + 16) * HSTR + col);
                }
                mma16816(acc[0], a0, a1, a2, a3, b0, b2);
                mma16816(acc[1], a0, a1, a2, a3, b1, b3);
                mma16816(acc[2], a0, a1, a2, a3, b4, b6);
                mma16816(acc[3], a0, a1, a2, a3, b5, b7);
            }
        }
        {
            const int gid = lane >> 2, t4 = lane & 3;
#pragma unroll
            for (int n = 0; n < 4; n++) {
                int c0 = n * 8 + t4 * 2;
                gsh[(wm + gid) * GSTR + c0] = acc[n][0];
                gsh[(wm + gid) * GSTR + c0 + 1] = acc[n][1];
                gsh[(wm + 8 + gid) * GSTR + c0] = acc[n][2];
                gsh[(wm + 8 + gid) * GSTR + c0 + 1] = acc[n][3];
            }
        }
        __syncthreads();

        float hval[2];
#pragma unroll
        for (int qq = 0; qq < 2; qq++) {
            int p = tid + qq * 256;
            int b = p >> 3, jj = p & 7;
            const float* g0 = gs + b * GSTR;
            const float* g1 = gs + (64 + b) * GSTR;
            float ig = g0[jj]      + g1[jj]      + xv[qq * 4 + 0];
            float fg = g0[8 + jj]  + g1[8 + jj]  + xv[qq * 4 + 1];
            float gg = g0[16 + jj] + g1[16 + jj] + xv[qq * 4 + 2];
            float og = g0[24 + jj] + g1[24 + jj] + xv[qq * 4 + 3];
            ig = sigmoid_fast(ig);
            fg = sigmoid_fast(fg);
            gg = tanh_fast(gg);
            og = sigmoid_fast(og);
            float c = fg * cs[p] + ig * gg;
            cs[p] = c;
            float h = og * tanh_fast(c);
            hval[qq] = h;
            g_hring[(size_t)((t + 1) & 3) * (Bq * Hq) + b * Hq + j0 + jj] = __float2half(h);
        }
        __syncthreads();
        // publish h_{t+1} availability BEFORE the (off-critical-path) output store
        if (tid == 0) {
            __threadfence();
            atomicAdd(&g_flag[(t + 1) * 8 + (bid >> 4)], 1u);
        }
#pragma unroll
        for (int qq = 0; qq < 2; qq++) {
            int p = tid + qq * 256;
            int b = p >> 3, jj = p & 7;
            size_t oidx = ((size_t)b * Tq + t) * Hq + j0 + jj;
            if (out32) out32[oidx] = hval[qq];
            else hbuf_out[oidx] = __float2half(hval[qq]);
        }
    }
}

extern "C" void kernel_launch(void* const* d_in, const int* in_sizes, int n_in,
                              void* d_out, int out_size) {
    const float* x   = (const float*)d_in[0];
    const float* Wih = (const float*)d_in[1];
    const float* Whh = (const float*)d_in[2];
    const float* bih = (const float*)d_in[3];
    const float* bhh = (const float*)d_in[4];
    float* out = (float*)d_out;

    cudaFuncSetAttribute(rec_kernel, cudaFuncAttributeMaxDynamicSharedMemorySize, RSMEM);

    prep_kernel<<<2048, 256>>>(x, Wih, Whh, bih, bhh);
    dummy_kernel<<<1, 1>>>();   // keeps ncu -s 5 window on rec_kernel (layer 1)

    __half* g_x16_p;  cudaGetSymbolAddress((void**)&g_x16_p,  g_x16);
    __half* g_h1_p;   cudaGetSymbolAddress((void**)&g_h1_p,   g_h1);
    __half* g_h2_p;   cudaGetSymbolAddress((void**)&g_h2_p,   g_h2);
    __half* g_wih_p;  cudaGetSymbolAddress((void**)&g_wih_p,  g_wih);
    __half* g_whh_p;  cudaGetSymbolAddress((void**)&g_whh_p,  g_whh);
    float*  g_bias_p; cudaGetSymbolAddress((void**)&g_bias_p, g_bias);
    float*  g_xp_p;   cudaGetSymbolAddress((void**)&g_xp_p,   g_xproj);

    dim3 pgrid(BT / 128, G4 / 128);

    proj_kernel<<<pgrid, 256>>>(g_x16_p, g_wih_p, g_bias_p, g_xp_p);
    rec_kernel<<<NCTA, 256, RSMEM>>>(g_xp_p, g_whh_p, g_h1_p, nullptr);

    proj_kernel<<<pgrid, 256>>>(g_h1_p, g_wih_p + (size_t)G4 * Iq, g_bias_p + G4, g_xp_p);
    rec_kernel<<<NCTA, 256, RSMEM>>>(g_xp_p, g_whh_p + (size_t)G4 * Hq, g_h2_p, nullptr);

    proj_kernel<<<pgrid, 256>>>(g_h2_p, g_wih_p + (size_t)2 * G4 * Iq, g_bias_p + 2 * G4, g_xp_p);
    rec_kernel<<<NCTA, 256, RSMEM>>>(g_xp_p, g_whh_p + (size_t)2 * G4 * Hq, nullptr, out);
}